// round 7
// baseline (speedup 1.0000x reference)
#include <cuda_runtime.h>
#include <math.h>

#define NN   50000
#define NE   800000
#define HD   128
#define NG   64
#define STEPS 8

// ---------------- device scratch (static globals: no allocation) ----------------
__device__ float d_h[NN * HD];
__device__ float d_y[NN * HD];
__device__ float d_kacc[NN * HD];
__device__ float d_T[NN * 256];
__device__ float d_Wio[128 * 256];   // [W_in | W_alt]
__device__ float d_Wode[128 * 256];  // [W_self | W_msg]
__device__ float d_Wtail[128 * 128]; // W_int[:128] + W_int[128:]
__device__ float d_degf[NN];
__device__ int   d_cnt[NN];
__device__ int   d_rowptr[NN + 1];
__device__ int   d_fill[NN];
__device__ int   d_col[NE];
__device__ float d_pooled[NG * HD];
__device__ float d_gcnt[NG];

// ---------------- small helpers ----------------
__device__ __forceinline__ float warp_sum(float v) {
#pragma unroll
    for (int o = 16; o > 0; o >>= 1) v += __shfl_xor_sync(0xffffffffu, v, o);
    return v;
}

__device__ __forceinline__ float gelu_tanh(float x) {
    float x3 = x * x * x;
    return 0.5f * x * (1.0f + tanhf(0.7978845608028654f * (x + 0.044715f * x3)));
}

__device__ __forceinline__ int clampi(int v, int lo, int hi) {
    return v < lo ? lo : (v > hi ? hi : v);
}

// ---------------- setup kernels ----------------
__global__ void k_zero() {
    int t = blockIdx.x * blockDim.x + threadIdx.x;
    if (t < NN) { d_cnt[t] = 0; d_fill[t] = 0; }
    if (t < NG * HD) d_pooled[t] = 0.0f;
    if (t < NG) d_gcnt[t] = 0.0f;
}

__global__ void k_count(const int* __restrict__ dst) {
    int e = blockIdx.x * blockDim.x + threadIdx.x;
    if (e < NE) atomicAdd(&d_cnt[clampi(dst[e], 0, NN - 1)], 1);
}

__global__ void k_scan() {
    __shared__ int sdata[1024];
    __shared__ int soff;
    int t = threadIdx.x;
    if (t == 0) soff = 0;
    __syncthreads();
    for (int base = 0; base < NN; base += 1024) {
        int i = base + t;
        int v = (i < NN) ? d_cnt[i] : 0;
        sdata[t] = v;
        __syncthreads();
#pragma unroll
        for (int off = 1; off < 1024; off <<= 1) {
            int add = (t >= off) ? sdata[t - off] : 0;
            __syncthreads();
            sdata[t] += add;
            __syncthreads();
        }
        int incl = sdata[t];
        if (i < NN) {
            d_rowptr[i] = soff + incl - v;          // exclusive prefix
            d_degf[i] = (float)(v > 0 ? v : 1);
        }
        __syncthreads();
        if (t == 0) soff += sdata[1023];
        __syncthreads();
    }
    if (t == 0) d_rowptr[NN] = soff;
}

__global__ void k_scatter(const int* __restrict__ src,
                          const int* __restrict__ dst) {
    int e = blockIdx.x * blockDim.x + threadIdx.x;
    if (e >= NE) return;
    int d = clampi(dst[e], 0, NN - 1);
    int pos = d_rowptr[d] + atomicAdd(&d_fill[d], 1);
    if (pos >= 0 && pos < NE) d_col[pos] = clampi(src[e], 0, NN - 1);
}

__global__ void k_pack(const float* __restrict__ Win, const float* __restrict__ Walt,
                       const float* __restrict__ Wself, const float* __restrict__ Wmsg,
                       const float* __restrict__ Wint) {
    int t = blockIdx.x * blockDim.x + threadIdx.x;
    if (t < 128 * 256) {
        int k = t >> 8, n = t & 255;
        d_Wio[t]  = (n < 128) ? Win[k * 128 + n]   : Walt[k * 128 + (n - 128)];
        d_Wode[t] = (n < 128) ? Wself[k * 128 + n] : Wmsg[k * 128 + (n - 128)];
    }
    if (t < 128 * 128) {
        int k = t >> 7, n = t & 127;
        d_Wtail[t] = Wint[k * 128 + n] + Wint[(k + 128) * 128 + n];
    }
}

// ---------------- fp32 SGEMM: C[M,N] = A[M,128] * B[128,N] ----------------
// BM=128, BN=128, BK=8, 256 threads, 8x8 micro-tile.
// selA: 0 = Aext, 1 = d_y, 2 = d_h     (device-global binding, no symbol API)
// selB: 0 = Bext, 1 = d_Wio, 2 = d_Wode, 3 = d_Wtail.  C is always d_T.
__global__ __launch_bounds__(256) void k_gemm(const float* __restrict__ Aext,
                                              const float* __restrict__ Bext,
                                              int selA, int selB,
                                              int M, int N) {
    const float* A = (selA == 0) ? Aext : ((selA == 1) ? (const float*)d_y
                                                       : (const float*)d_h);
    const float* B = (selB == 0) ? Bext
                   : (selB == 1) ? (const float*)d_Wio
                   : (selB == 2) ? (const float*)d_Wode
                                 : (const float*)d_Wtail;
    float* C = d_T;

    __shared__ float As[8][132];
    __shared__ float Bs[8][132];
    int tid = threadIdx.x;
    int tx = tid & 15, ty = tid >> 4;
    int m0 = blockIdx.x * 128;
    int n0 = blockIdx.y * 128;

    float acc[8][8];
#pragma unroll
    for (int i = 0; i < 8; i++)
#pragma unroll
        for (int j = 0; j < 8; j++) acc[i][j] = 0.0f;

    int ar = tid >> 1;            // 0..127 row within tile
    int ah = (tid & 1) * 4;       // 0 or 4 (k offset)
    int br = tid >> 5;            // 0..7
    int bc = (tid & 31) * 4;      // 0..124

    for (int k0 = 0; k0 < 128; k0 += 8) {
        float4 av = make_float4(0.f, 0.f, 0.f, 0.f);
        if (m0 + ar < M)
            av = *(const float4*)&A[(size_t)(m0 + ar) * 128 + k0 + ah];
        As[ah + 0][ar] = av.x;
        As[ah + 1][ar] = av.y;
        As[ah + 2][ar] = av.z;
        As[ah + 3][ar] = av.w;
        float4 bv = *(const float4*)&B[(size_t)(k0 + br) * N + n0 + bc];
        *(float4*)&Bs[br][bc] = bv;
        __syncthreads();
#pragma unroll
        for (int kk = 0; kk < 8; kk++) {
            float a_r[8], b_r[8];
            float4 a0 = *(const float4*)&As[kk][ty * 8];
            float4 a1 = *(const float4*)&As[kk][ty * 8 + 4];
            float4 b0 = *(const float4*)&Bs[kk][tx * 8];
            float4 b1 = *(const float4*)&Bs[kk][tx * 8 + 4];
            a_r[0] = a0.x; a_r[1] = a0.y; a_r[2] = a0.z; a_r[3] = a0.w;
            a_r[4] = a1.x; a_r[5] = a1.y; a_r[6] = a1.z; a_r[7] = a1.w;
            b_r[0] = b0.x; b_r[1] = b0.y; b_r[2] = b0.z; b_r[3] = b0.w;
            b_r[4] = b1.x; b_r[5] = b1.y; b_r[6] = b1.z; b_r[7] = b1.w;
#pragma unroll
            for (int i = 0; i < 8; i++)
#pragma unroll
                for (int j = 0; j < 8; j++)
                    acc[i][j] += a_r[i] * b_r[j];
        }
        __syncthreads();
    }

#pragma unroll
    for (int i = 0; i < 8; i++) {
        int row = m0 + ty * 8 + i;
        if (row < M) {
            float4 o0 = make_float4(acc[i][0], acc[i][1], acc[i][2], acc[i][3]);
            float4 o1 = make_float4(acc[i][4], acc[i][5], acc[i][6], acc[i][7]);
            *(float4*)&C[(size_t)row * N + n0 + tx * 8]     = o0;
            *(float4*)&C[(size_t)row * N + n0 + tx * 8 + 4] = o1;
        }
    }
}

// ---------------- head: LN + gelu on both halves of T, mix -> h, y ----------------
__device__ __forceinline__ void ln_gelu4(float4 t, const float* __restrict__ b,
                                         const float* __restrict__ g,
                                         const float* __restrict__ be,
                                         int lane, float out[4]) {
    float4 bb = *(const float4*)&b[lane * 4];
    float4 gg = *(const float4*)&g[lane * 4];
    float4 ee = *(const float4*)&be[lane * 4];
    float v0 = t.x + bb.x, v1 = t.y + bb.y, v2 = t.z + bb.z, v3 = t.w + bb.w;
    float m = warp_sum(v0 + v1 + v2 + v3) * (1.0f / 128.0f);
    float q = warp_sum(v0 * v0 + v1 * v1 + v2 * v2 + v3 * v3) * (1.0f / 128.0f);
    float var = q - m * m;
    float r = rsqrtf(var + 1e-5f);
    out[0] = gelu_tanh((v0 - m) * r * gg.x + ee.x);
    out[1] = gelu_tanh((v1 - m) * r * gg.y + ee.y);
    out[2] = gelu_tanh((v2 - m) * r * gg.z + ee.z);
    out[3] = gelu_tanh((v3 - m) * r * gg.w + ee.w);
}

__global__ __launch_bounds__(256) void k_head(
        const float* __restrict__ bin, const float* __restrict__ gin,
        const float* __restrict__ bein,
        const float* __restrict__ balt, const float* __restrict__ galt,
        const float* __restrict__ bealt,
        const float* __restrict__ alpha_p, const float* __restrict__ beta_p) {
    int w = (blockIdx.x * blockDim.x + threadIdx.x) >> 5;
    if (w >= NN) return;
    int lane = threadIdx.x & 31;
    float al = *alpha_p, bt = *beta_p;
    float nrm = sqrtf(al * al + bt * bt);
    float s0 = fabsf(al) / nrm, s1 = fabsf(bt) / nrm;

    float4 t0 = *(const float4*)&d_T[(size_t)w * 256 + lane * 4];
    float4 t1 = *(const float4*)&d_T[(size_t)w * 256 + 128 + lane * 4];
    float g0[4], g1[4];
    ln_gelu4(t0, bin, gin, bein, lane, g0);
    ln_gelu4(t1, balt, galt, bealt, lane, g1);

    float4 hv;
    hv.x = s0 * g0[0] + s1 * g1[0];
    hv.y = s0 * g0[1] + s1 * g1[1];
    hv.z = s0 * g0[2] + s1 * g1[2];
    hv.w = s0 * g0[3] + s1 * g1[3];
    size_t off = (size_t)w * HD + lane * 4;
    *(float4*)&d_h[off] = hv;
    *(float4*)&d_y[off] = hv;
}

// ---------------- fused SpMM + tanh + RK4 bookkeeping ----------------
// One warp per node. All lanes read the same column index (broadcast LDG),
// then each lane reads 16B of the 512B neighbor row (coalesced). 2-way
// unrolled with independent accumulators for MLP=2.
__global__ __launch_bounds__(256) void k_spmm(const float* __restrict__ bode,
                                              float wgt, float cnext,
                                              int first, int last, float dt6) {
    int w = (blockIdx.x * blockDim.x + threadIdx.x) >> 5;
    if (w >= NN) return;
    int lane = threadIdx.x & 31;

    float4 self = *(const float4*)&d_T[(size_t)w * 256 + lane * 4];
    float4 agg0 = make_float4(0.f, 0.f, 0.f, 0.f);
    float4 agg1 = make_float4(0.f, 0.f, 0.f, 0.f);
    int beg = d_rowptr[w], end = d_rowptr[w + 1];

    int ii = beg;
    for (; ii + 2 <= end; ii += 2) {
        int s0 = __ldg(&d_col[ii]);
        int s1 = __ldg(&d_col[ii + 1]);
        float4 m0 = *(const float4*)&d_T[(size_t)s0 * 256 + 128 + lane * 4];
        float4 m1 = *(const float4*)&d_T[(size_t)s1 * 256 + 128 + lane * 4];
        agg0.x += m0.x; agg0.y += m0.y; agg0.z += m0.z; agg0.w += m0.w;
        agg1.x += m1.x; agg1.y += m1.y; agg1.z += m1.z; agg1.w += m1.w;
    }
    if (ii < end) {
        int s0 = __ldg(&d_col[ii]);
        float4 m0 = *(const float4*)&d_T[(size_t)s0 * 256 + 128 + lane * 4];
        agg0.x += m0.x; agg0.y += m0.y; agg0.z += m0.z; agg0.w += m0.w;
    }
    float4 agg = make_float4(agg0.x + agg1.x, agg0.y + agg1.y,
                             agg0.z + agg1.z, agg0.w + agg1.w);

    float inv = 1.0f / d_degf[w];
    float4 bb = *(const float4*)&bode[lane * 4];
    float4 kv;
    kv.x = tanhf(self.x + agg.x * inv + bb.x);
    kv.y = tanhf(self.y + agg.y * inv + bb.y);
    kv.z = tanhf(self.z + agg.z * inv + bb.z);
    kv.w = tanhf(self.w + agg.w * inv + bb.w);

    size_t off = (size_t)w * HD + lane * 4;
    float4 ka;
    if (first) {
        ka.x = wgt * kv.x; ka.y = wgt * kv.y; ka.z = wgt * kv.z; ka.w = wgt * kv.w;
    } else {
        ka = *(float4*)&d_kacc[off];
        ka.x += wgt * kv.x; ka.y += wgt * kv.y; ka.z += wgt * kv.z; ka.w += wgt * kv.w;
    }
    *(float4*)&d_kacc[off] = ka;

    float4 hh = *(const float4*)&d_h[off];
    if (last) {
        float4 hn;
        hn.x = hh.x + dt6 * ka.x; hn.y = hh.y + dt6 * ka.y;
        hn.z = hh.z + dt6 * ka.z; hn.w = hh.w + dt6 * ka.w;
        *(float4*)&d_h[off] = hn;
        *(float4*)&d_y[off] = hn;
    } else {
        float4 yn;
        yn.x = hh.x + cnext * kv.x; yn.y = hh.y + cnext * kv.y;
        yn.z = hh.z + cnext * kv.z; yn.w = hh.w + cnext * kv.w;
        *(float4*)&d_y[off] = yn;
    }
}

// ---------------- tail: LN + tanh + interference gate + collapse ----------------
__global__ __launch_bounds__(256) void k_tail(
        const float* __restrict__ bint, const float* __restrict__ gint,
        const float* __restrict__ beint,
        const float* __restrict__ alpha_p, const float* __restrict__ beta_p,
        const float* __restrict__ phase_p) {
    int w = (blockIdx.x * blockDim.x + threadIdx.x) >> 5;
    if (w >= NN) return;
    int lane = threadIdx.x & 31;
    float al = *alpha_p, bt = *beta_p, ph = *phase_p;
    float n2 = al * al + bt * bt;
    float p0 = al * al / n2, p1 = bt * bt / n2;
    float interf = 2.0f * sqrtf(p0 * p1) * cosf(ph);
    float gate = (fabsf(interf) > 0.01f) ? interf : 0.0f;
    float coll = (p0 > p1) ? 1.0f : cosf(ph);

    float4 u = *(const float4*)&d_T[(size_t)w * HD + lane * 4];
    float4 bb = *(const float4*)&bint[lane * 4];
    float4 gg = *(const float4*)&gint[lane * 4];
    float4 ee = *(const float4*)&beint[lane * 4];
    float v0 = u.x + bb.x, v1 = u.y + bb.y, v2 = u.z + bb.z, v3 = u.w + bb.w;
    float m = warp_sum(v0 + v1 + v2 + v3) * (1.0f / 128.0f);
    float q = warp_sum(v0 * v0 + v1 * v1 + v2 * v2 + v3 * v3) * (1.0f / 128.0f);
    float r = rsqrtf(q - m * m + 1e-5f);
    float hi0 = tanhf((v0 - m) * r * gg.x + ee.x);
    float hi1 = tanhf((v1 - m) * r * gg.y + ee.y);
    float hi2 = tanhf((v2 - m) * r * gg.z + ee.z);
    float hi3 = tanhf((v3 - m) * r * gg.w + ee.w);

    size_t off = (size_t)w * HD + lane * 4;
    float4 hh = *(const float4*)&d_h[off];
    float4 hf;
    hf.x = (hh.x + gate * hi0) * coll;
    hf.y = (hh.y + gate * hi1) * coll;
    hf.z = (hh.z + gate * hi2) * coll;
    hf.w = (hh.w + gate * hi3) * coll;
    *(float4*)&d_y[off] = hf;
}

// ---------------- pooling ----------------
__global__ __launch_bounds__(256) void k_pool(const int* __restrict__ batch) {
    int w = (blockIdx.x * blockDim.x + threadIdx.x) >> 5;
    if (w >= NN) return;
    int lane = threadIdx.x & 31;
    int g = clampi(batch[w], 0, NG - 1);
    float4 v = *(const float4*)&d_T[(size_t)w * HD + lane * 4];
    atomicAdd(&d_pooled[g * HD + lane * 4 + 0], v.x);
    atomicAdd(&d_pooled[g * HD + lane * 4 + 1], v.y);
    atomicAdd(&d_pooled[g * HD + lane * 4 + 2], v.z);
    atomicAdd(&d_pooled[g * HD + lane * 4 + 3], v.w);
    if (lane == 0) atomicAdd(&d_gcnt[g], 1.0f);
}

__global__ void k_finish(const float* __restrict__ bout, float* __restrict__ out) {
    int t = blockIdx.x * blockDim.x + threadIdx.x;
    if (t >= NG * HD) return;
    int c = t & 127;
    float cg = d_gcnt[t >> 7];
    out[t] = (cg > 0.0f) ? d_pooled[t] / cg + bout[c] : 0.0f;
}

// ---------------- host ----------------
extern "C" void kernel_launch(void* const* d_in, const int* in_sizes, int n_in,
                              void* d_out, int out_size) {
    const float* x     = (const float*)d_in[0];
    const int*   ei    = (const int*)d_in[1];    // int32 on device (JAX default x64 disabled)
    const int*   batch = (const int*)d_in[2];    // int32
    const float* alpha = (const float*)d_in[3];
    const float* beta  = (const float*)d_in[4];
    const float* phase = (const float*)d_in[5];
    const float* Win   = (const float*)d_in[6];
    const float* bin   = (const float*)d_in[7];
    const float* gin   = (const float*)d_in[8];
    const float* bein  = (const float*)d_in[9];
    const float* Walt  = (const float*)d_in[10];
    const float* balt  = (const float*)d_in[11];
    const float* galt  = (const float*)d_in[12];
    const float* bealt = (const float*)d_in[13];
    const float* Wself = (const float*)d_in[14];
    const float* Wmsg  = (const float*)d_in[15];
    const float* bode  = (const float*)d_in[16];
    const float* Wint  = (const float*)d_in[17];
    const float* bint  = (const float*)d_in[18];
    const float* gint  = (const float*)d_in[19];
    const float* beint = (const float*)d_in[20];
    const float* Wout  = (const float*)d_in[21];
    const float* bout  = (const float*)d_in[22];
    float* out = (float*)d_out;

    const int WB = (NN * 32 + 255) / 256;       // warp-per-node kernels: 6250 blocks
    const dim3 g2((NN + 127) / 128, 2), g1((NN + 127) / 128, 1);
    const float dt = 1.0f / (float)STEPS;

    k_zero<<<(NN + 255) / 256, 256>>>();
    k_count<<<(NE + 255) / 256, 256>>>(ei + NE);
    k_scan<<<1, 1024>>>();
    k_scatter<<<(NE + 255) / 256, 256>>>(ei, ei + NE);
    k_pack<<<(128 * 256 + 255) / 256, 256>>>(Win, Walt, Wself, Wmsg, Wint);

    // head: T = x @ [W_in | W_alt]; LN+gelu+mix
    k_gemm<<<g2, 256>>>(x, nullptr, 0, 1, NN, 256);
    k_head<<<WB, 256>>>(bin, gin, bein, balt, galt, bealt, alpha, beta);

    // RK4 neural ODE
    for (int s = 0; s < STEPS; s++) {
        k_gemm<<<g2, 256>>>(nullptr, nullptr, 1, 2, NN, 256);
        k_spmm<<<WB, 256>>>(bode, 1.0f, 0.5f * dt, 1, 0, 0.0f);
        k_gemm<<<g2, 256>>>(nullptr, nullptr, 1, 2, NN, 256);
        k_spmm<<<WB, 256>>>(bode, 2.0f, 0.5f * dt, 0, 0, 0.0f);
        k_gemm<<<g2, 256>>>(nullptr, nullptr, 1, 2, NN, 256);
        k_spmm<<<WB, 256>>>(bode, 2.0f, dt, 0, 0, 0.0f);
        k_gemm<<<g2, 256>>>(nullptr, nullptr, 1, 2, NN, 256);
        k_spmm<<<WB, 256>>>(bode, 1.0f, 0.0f, 0, 1, dt / 6.0f);
    }

    // tail: U = h @ (W_int_top + W_int_bot); LN+tanh+gate+collapse -> y; V = y @ W_out
    k_gemm<<<g1, 256>>>(nullptr, nullptr, 2, 3, NN, 128);
    k_tail<<<WB, 256>>>(bint, gint, beint, alpha, beta, phase);
    k_gemm<<<g1, 256>>>(nullptr, Wout, 1, 0, NN, 128);

    // pooled mean per graph
    k_pool<<<WB, 256>>>(batch);
    k_finish<<<32, 256>>>(bout, out);
}

// round 12
// speedup vs baseline: 1.6214x; 1.6214x over previous
#include <cuda_runtime.h>
#include <cuda_bf16.h>
#include <math.h>

#define NN   50000
#define NE   800000
#define HD   128
#define NG   64
#define STEPS 8

// ---------------- device scratch (static globals: no allocation) ----------------
__device__ float d_h[NN * HD];
__device__ float d_y[NN * HD];
__device__ float d_kacc[NN * HD];
__device__ float d_T[NN * 256];
// split-bf16 packed weights: layout [n][64] uint32, each uint32 = {lo16=bf16(W[2kp][n]), hi16=bf16(W[2kp+1][n])}
__device__ unsigned int d_WioH[256 * 64],  d_WioL[256 * 64];   // [W_in | W_alt]
__device__ unsigned int d_WodeH[256 * 64], d_WodeL[256 * 64];  // [W_self | W_msg]
__device__ unsigned int d_WtailH[128 * 64], d_WtailL[128 * 64]; // W_int[:128]+W_int[128:]
__device__ unsigned int d_WoutH[128 * 64], d_WoutL[128 * 64];
__device__ float d_degf[NN];
__device__ int   d_cnt[NN];
__device__ int   d_rowptr[NN + 1];
__device__ int   d_fill[NN];
__device__ int   d_col[NE];
__device__ float d_pooled[NG * HD];
__device__ float d_gcnt[NG];

// ---------------- small helpers ----------------
__device__ __forceinline__ float warp_sum(float v) {
#pragma unroll
    for (int o = 16; o > 0; o >>= 1) v += __shfl_xor_sync(0xffffffffu, v, o);
    return v;
}

__device__ __forceinline__ float gelu_tanh(float x) {
    float x3 = x * x * x;
    return 0.5f * x * (1.0f + tanhf(0.7978845608028654f * (x + 0.044715f * x3)));
}

__device__ __forceinline__ int clampi(int v, int lo, int hi) {
    return v < lo ? lo : (v > hi ? hi : v);
}

// pack two floats into bf16x2 (a -> low half / first element, b -> high half)
__device__ __forceinline__ unsigned int pack_bf2(float a, float b) {
    unsigned int r;
    asm("cvt.rn.bf16x2.f32 %0, %1, %2;" : "=r"(r) : "f"(b), "f"(a));
    return r;
}

// split (a,b) into hi-pair and residual lo-pair
__device__ __forceinline__ void split2(float a, float b, unsigned int& hi, unsigned int& lo) {
    float ah = __bfloat162float(__float2bfloat16(a));
    float bh = __bfloat162float(__float2bfloat16(b));
    hi = pack_bf2(a, b);
    lo = pack_bf2(a - ah, b - bh);
}

__device__ __forceinline__ void mma16816(float c[4],
                                         unsigned int a0, unsigned int a1,
                                         unsigned int a2, unsigned int a3,
                                         unsigned int b0, unsigned int b1) {
    asm volatile(
        "mma.sync.aligned.m16n8k16.row.col.f32.bf16.bf16.f32 "
        "{%0,%1,%2,%3}, {%4,%5,%6,%7}, {%8,%9}, {%0,%1,%2,%3};"
        : "+f"(c[0]), "+f"(c[1]), "+f"(c[2]), "+f"(c[3])
        : "r"(a0), "r"(a1), "r"(a2), "r"(a3), "r"(b0), "r"(b1));
}

// ---------------- setup kernels ----------------
__global__ void k_zero() {
    int t = blockIdx.x * blockDim.x + threadIdx.x;
    if (t < NN) { d_cnt[t] = 0; d_fill[t] = 0; }
    if (t < NG * HD) d_pooled[t] = 0.0f;
    if (t < NG) d_gcnt[t] = 0.0f;
}

__global__ void k_count(const int* __restrict__ dst) {
    int e = blockIdx.x * blockDim.x + threadIdx.x;
    if (e < NE) atomicAdd(&d_cnt[clampi(dst[e], 0, NN - 1)], 1);
}

__global__ void k_scan() {
    __shared__ int sdata[1024];
    __shared__ int soff;
    int t = threadIdx.x;
    if (t == 0) soff = 0;
    __syncthreads();
    for (int base = 0; base < NN; base += 1024) {
        int i = base + t;
        int v = (i < NN) ? d_cnt[i] : 0;
        sdata[t] = v;
        __syncthreads();
#pragma unroll
        for (int off = 1; off < 1024; off <<= 1) {
            int add = (t >= off) ? sdata[t - off] : 0;
            __syncthreads();
            sdata[t] += add;
            __syncthreads();
        }
        int incl = sdata[t];
        if (i < NN) {
            d_rowptr[i] = soff + incl - v;          // exclusive prefix
            d_degf[i] = (float)(v > 0 ? v : 1);
        }
        __syncthreads();
        if (t == 0) soff += sdata[1023];
        __syncthreads();
    }
    if (t == 0) d_rowptr[NN] = soff;
}

__global__ void k_scatter(const int* __restrict__ src,
                          const int* __restrict__ dst) {
    int e = blockIdx.x * blockDim.x + threadIdx.x;
    if (e >= NE) return;
    int d = clampi(dst[e], 0, NN - 1);
    int pos = d_rowptr[d] + atomicAdd(&d_fill[d], 1);
    if (pos >= 0 && pos < NE) d_col[pos] = clampi(src[e], 0, NN - 1);
}

// pack + split weights into n-major k-pair-packed bf16 buffers
__global__ void k_pack(const float* __restrict__ Win, const float* __restrict__ Walt,
                       const float* __restrict__ Wself, const float* __restrict__ Wmsg,
                       const float* __restrict__ Wint, const float* __restrict__ Wout) {
    int t = blockIdx.x * blockDim.x + threadIdx.x;
    if (t < 256 * 64) {
        int n = t >> 6, kp = t & 63;
        int k0 = 2 * kp, k1 = 2 * kp + 1;
        float w0, w1;
        // Wio
        if (n < 128) { w0 = Win[k0 * 128 + n];  w1 = Win[k1 * 128 + n]; }
        else         { w0 = Walt[k0 * 128 + n - 128]; w1 = Walt[k1 * 128 + n - 128]; }
        split2(w0, w1, d_WioH[t], d_WioL[t]);
        // Wode
        if (n < 128) { w0 = Wself[k0 * 128 + n]; w1 = Wself[k1 * 128 + n]; }
        else         { w0 = Wmsg[k0 * 128 + n - 128]; w1 = Wmsg[k1 * 128 + n - 128]; }
        split2(w0, w1, d_WodeH[t], d_WodeL[t]);
    }
    if (t < 128 * 64) {
        int n = t >> 6, kp = t & 63;
        int k0 = 2 * kp, k1 = 2 * kp + 1;
        float w0 = Wint[k0 * 128 + n] + Wint[(k0 + 128) * 128 + n];
        float w1 = Wint[k1 * 128 + n] + Wint[(k1 + 128) * 128 + n];
        split2(w0, w1, d_WtailH[t], d_WtailL[t]);
        split2(Wout[k0 * 128 + n], Wout[k1 * 128 + n], d_WoutH[t], d_WoutL[t]);
    }
}

// ---------------- split-bf16 tensor-core GEMM: C[M,N] = A[M,128] * B[128,N] ----------------
// BM=128, BN=128, K staged in 4 chunks of 32. 256 threads = 8 warps, each 64x32 C tile.
// A fp32 -> split bf16 in smem; B preconverted. 3-term: AhBh + AhBl + AlBh, fp32 accum.
// selA: 0 = Aext, 1 = d_y, 2 = d_h.  selB: 1 = Wio, 2 = Wode, 3 = Wtail, 4 = Wout.  C = d_T.
#define SROW 20   // uint32 stride per 32-k stage row (16 pairs + 4 pad): conflict-free frags
__global__ __launch_bounds__(256) void k_gemm(const float* __restrict__ Aext,
                                              int selA, int selB, int M, int N) {
    const float* A = (selA == 0) ? Aext : ((selA == 1) ? (const float*)d_y
                                                       : (const float*)d_h);
    const unsigned int* Bh = (selB == 1) ? d_WioH
                           : (selB == 2) ? d_WodeH
                           : (selB == 3) ? d_WtailH : d_WoutH;
    const unsigned int* Bl = (selB == 1) ? d_WioL
                           : (selB == 2) ? d_WodeL
                           : (selB == 3) ? d_WtailL : d_WoutL;

    __shared__ unsigned int AsH[128 * SROW], AsL[128 * SROW];
    __shared__ unsigned int BsH[128 * SROW], BsL[128 * SROW];

    int tid = threadIdx.x;
    int wid = tid >> 5, lane = tid & 31;
    int g = lane >> 2, tg = lane & 3;
    int wm = (wid & 1) * 64;          // warp m-offset within 128
    int wn = (wid >> 1) * 32;         // warp n-offset within 128
    int m0 = blockIdx.x * 128;
    int n0 = blockIdx.y * 128;

    float c[4][4][4];
#pragma unroll
    for (int mb = 0; mb < 4; mb++)
#pragma unroll
        for (int nb = 0; nb < 4; nb++)
#pragma unroll
            for (int i = 0; i < 4; i++) c[mb][nb][i] = 0.0f;

    for (int ks = 0; ks < 4; ks++) {            // k0 = ks*32
        __syncthreads();                         // protect previous stage smem
        // stage A: 128 rows x 32 floats -> split bf16 pairs (1024 float4 loads)
#pragma unroll
        for (int i = 0; i < 4; i++) {
            int idx = tid + i * 256;             // 0..1023
            int row = idx >> 3, q = idx & 7;     // q: float4 index within 32 floats
            float4 v = make_float4(0.f, 0.f, 0.f, 0.f);
            if (m0 + row < M)
                v = *(const float4*)&A[(size_t)(m0 + row) * 128 + ks * 32 + q * 4];
            unsigned int h0, l0, h1, l1;
            split2(v.x, v.y, h0, l0);
            split2(v.z, v.w, h1, l1);
            AsH[row * SROW + q * 2]     = h0;
            AsH[row * SROW + q * 2 + 1] = h1;
            AsL[row * SROW + q * 2]     = l0;
            AsL[row * SROW + q * 2 + 1] = l1;
        }
        // stage B: 128 n-rows x 16 k-pairs = 2048 elements -> 8 iterations
#pragma unroll
        for (int i = 0; i < 8; i++) {
            int idx = tid + i * 256;             // 0..2047
            int n = idx >> 4, kp = idx & 15;     // n: 0..127
            BsH[n * SROW + kp] = Bh[(size_t)(n0 + n) * 64 + ks * 16 + kp];
            BsL[n * SROW + kp] = Bl[(size_t)(n0 + n) * 64 + ks * 16 + kp];
        }
        __syncthreads();

#pragma unroll
        for (int kc = 0; kc < 2; kc++) {         // two k16 chunks per stage
            int kb = kc * 8;                     // pair offset
            unsigned int aH[4][4], aL[4][4], bH[4][2], bL[4][2];
#pragma unroll
            for (int mb = 0; mb < 4; mb++) {
                int r0 = (wm + mb * 16 + g) * SROW + kb + tg;
                int r1 = (wm + mb * 16 + 8 + g) * SROW + kb + tg;
                aH[mb][0] = AsH[r0];     aH[mb][1] = AsH[r1];
                aH[mb][2] = AsH[r0 + 4]; aH[mb][3] = AsH[r1 + 4];
                aL[mb][0] = AsL[r0];     aL[mb][1] = AsL[r1];
                aL[mb][2] = AsL[r0 + 4]; aL[mb][3] = AsL[r1 + 4];
            }
#pragma unroll
            for (int nb = 0; nb < 4; nb++) {
                int nr = (wn + nb * 8 + g) * SROW + kb + tg;
                bH[nb][0] = BsH[nr]; bH[nb][1] = BsH[nr + 4];
                bL[nb][0] = BsL[nr]; bL[nb][1] = BsL[nr + 4];
            }
#pragma unroll
            for (int mb = 0; mb < 4; mb++)
#pragma unroll
                for (int nb = 0; nb < 4; nb++) {
                    mma16816(c[mb][nb], aH[mb][0], aH[mb][1], aH[mb][2], aH[mb][3],
                             bH[nb][0], bH[nb][1]);
                    mma16816(c[mb][nb], aH[mb][0], aH[mb][1], aH[mb][2], aH[mb][3],
                             bL[nb][0], bL[nb][1]);
                    mma16816(c[mb][nb], aL[mb][0], aL[mb][1], aL[mb][2], aL[mb][3],
                             bH[nb][0], bH[nb][1]);
                }
        }
    }

    // store C
#pragma unroll
    for (int mb = 0; mb < 4; mb++) {
        int r0 = m0 + wm + mb * 16 + g;
        int r1 = r0 + 8;
#pragma unroll
        for (int nb = 0; nb < 4; nb++) {
            int col = n0 + wn + nb * 8 + 2 * tg;
            if (r0 < M) {
                float2 v0 = make_float2(c[mb][nb][0], c[mb][nb][1]);
                *(float2*)&d_T[(size_t)r0 * N + col] = v0;
            }
            if (r1 < M) {
                float2 v1 = make_float2(c[mb][nb][2], c[mb][nb][3]);
                *(float2*)&d_T[(size_t)r1 * N + col] = v1;
            }
        }
    }
}

// ---------------- head: LN + gelu on both halves of T, mix -> h, y ----------------
__device__ __forceinline__ void ln_gelu4(float4 t, const float* __restrict__ b,
                                         const float* __restrict__ g,
                                         const float* __restrict__ be,
                                         int lane, float out[4]) {
    float4 bb = *(const float4*)&b[lane * 4];
    float4 gg = *(const float4*)&g[lane * 4];
    float4 ee = *(const float4*)&be[lane * 4];
    float v0 = t.x + bb.x, v1 = t.y + bb.y, v2 = t.z + bb.z, v3 = t.w + bb.w;
    float m = warp_sum(v0 + v1 + v2 + v3) * (1.0f / 128.0f);
    float q = warp_sum(v0 * v0 + v1 * v1 + v2 * v2 + v3 * v3) * (1.0f / 128.0f);
    float var = q - m * m;
    float r = rsqrtf(var + 1e-5f);
    out[0] = gelu_tanh((v0 - m) * r * gg.x + ee.x);
    out[1] = gelu_tanh((v1 - m) * r * gg.y + ee.y);
    out[2] = gelu_tanh((v2 - m) * r * gg.z + ee.z);
    out[3] = gelu_tanh((v3 - m) * r * gg.w + ee.w);
}

__global__ __launch_bounds__(256) void k_head(
        const float* __restrict__ bin, const float* __restrict__ gin,
        const float* __restrict__ bein,
        const float* __restrict__ balt, const float* __restrict__ galt,
        const float* __restrict__ bealt,
        const float* __restrict__ alpha_p, const float* __restrict__ beta_p) {
    int w = (blockIdx.x * blockDim.x + threadIdx.x) >> 5;
    if (w >= NN) return;
    int lane = threadIdx.x & 31;
    float al = *alpha_p, bt = *beta_p;
    float nrm = sqrtf(al * al + bt * bt);
    float s0 = fabsf(al) / nrm, s1 = fabsf(bt) / nrm;

    float4 t0 = *(const float4*)&d_T[(size_t)w * 256 + lane * 4];
    float4 t1 = *(const float4*)&d_T[(size_t)w * 256 + 128 + lane * 4];
    float g0[4], g1[4];
    ln_gelu4(t0, bin, gin, bein, lane, g0);
    ln_gelu4(t1, balt, galt, bealt, lane, g1);

    float4 hv;
    hv.x = s0 * g0[0] + s1 * g1[0];
    hv.y = s0 * g0[1] + s1 * g1[1];
    hv.z = s0 * g0[2] + s1 * g1[2];
    hv.w = s0 * g0[3] + s1 * g1[3];
    size_t off = (size_t)w * HD + lane * 4;
    *(float4*)&d_h[off] = hv;
    *(float4*)&d_y[off] = hv;
}

// ---------------- fused SpMM + tanh + RK4 bookkeeping ----------------
// One warp per node; 4-way unrolled gather with independent accumulators (MLP=4).
__global__ __launch_bounds__(256) void k_spmm(const float* __restrict__ bode,
                                              float wgt, float cnext,
                                              int first, int last, float dt6) {
    int w = (blockIdx.x * blockDim.x + threadIdx.x) >> 5;
    if (w >= NN) return;
    int lane = threadIdx.x & 31;

    float4 self = *(const float4*)&d_T[(size_t)w * 256 + lane * 4];
    float4 ag0 = make_float4(0.f, 0.f, 0.f, 0.f);
    float4 ag1 = make_float4(0.f, 0.f, 0.f, 0.f);
    float4 ag2 = make_float4(0.f, 0.f, 0.f, 0.f);
    float4 ag3 = make_float4(0.f, 0.f, 0.f, 0.f);
    int beg = d_rowptr[w], end = d_rowptr[w + 1];

    int ii = beg;
    for (; ii + 4 <= end; ii += 4) {
        int s0 = __ldg(&d_col[ii]);
        int s1 = __ldg(&d_col[ii + 1]);
        int s2 = __ldg(&d_col[ii + 2]);
        int s3 = __ldg(&d_col[ii + 3]);
        float4 m0 = *(const float4*)&d_T[(size_t)s0 * 256 + 128 + lane * 4];
        float4 m1 = *(const float4*)&d_T[(size_t)s1 * 256 + 128 + lane * 4];
        float4 m2 = *(const float4*)&d_T[(size_t)s2 * 256 + 128 + lane * 4];
        float4 m3 = *(const float4*)&d_T[(size_t)s3 * 256 + 128 + lane * 4];
        ag0.x += m0.x; ag0.y += m0.y; ag0.z += m0.z; ag0.w += m0.w;
        ag1.x += m1.x; ag1.y += m1.y; ag1.z += m1.z; ag1.w += m1.w;
        ag2.x += m2.x; ag2.y += m2.y; ag2.z += m2.z; ag2.w += m2.w;
        ag3.x += m3.x; ag3.y += m3.y; ag3.z += m3.z; ag3.w += m3.w;
    }
    for (; ii < end; ii++) {
        int s0 = __ldg(&d_col[ii]);
        float4 m0 = *(const float4*)&d_T[(size_t)s0 * 256 + 128 + lane * 4];
        ag0.x += m0.x; ag0.y += m0.y; ag0.z += m0.z; ag0.w += m0.w;
    }
    float4 agg = make_float4((ag0.x + ag1.x) + (ag2.x + ag3.x),
                             (ag0.y + ag1.y) + (ag2.y + ag3.y),
                             (ag0.z + ag1.z) + (ag2.z + ag3.z),
                             (ag0.w + ag1.w) + (ag2.w + ag3.w));

    float inv = 1.0f / d_degf[w];
    float4 bb = *(const float4*)&bode[lane * 4];
    float4 kv;
    kv.x = tanhf(self.x + agg.x * inv + bb.x);
    kv.y = tanhf(self.y + agg.y * inv + bb.y);
    kv.z = tanhf(self.z + agg.z * inv + bb.z);
    kv.w = tanhf(self.w + agg.w * inv + bb.w);

    size_t off = (size_t)w * HD + lane * 4;
    float4 ka;
    if (first) {
        ka.x = wgt * kv.x; ka.y = wgt * kv.y; ka.z = wgt * kv.z; ka.w = wgt * kv.w;
    } else {
        ka = *(float4*)&d_kacc[off];
        ka.x += wgt * kv.x; ka.y += wgt * kv.y; ka.z += wgt * kv.z; ka.w += wgt * kv.w;
    }
    *(float4*)&d_kacc[off] = ka;

    float4 hh = *(const float4*)&d_h[off];
    if (last) {
        float4 hn;
        hn.x = hh.x + dt6 * ka.x; hn.y = hh.y + dt6 * ka.y;
        hn.z = hh.z + dt6 * ka.z; hn.w = hh.w + dt6 * ka.w;
        *(float4*)&d_h[off] = hn;
        *(float4*)&d_y[off] = hn;
    } else {
        float4 yn;
        yn.x = hh.x + cnext * kv.x; yn.y = hh.y + cnext * kv.y;
        yn.z = hh.z + cnext * kv.z; yn.w = hh.w + cnext * kv.w;
        *(float4*)&d_y[off] = yn;
    }
}

// ---------------- tail: LN + tanh + interference gate + collapse ----------------
__global__ __launch_bounds__(256) void k_tail(
        const float* __restrict__ bint, const float* __restrict__ gint,
        const float* __restrict__ beint,
        const float* __restrict__ alpha_p, const float* __restrict__ beta_p,
        const float* __restrict__ phase_p) {
    int w = (blockIdx.x * blockDim.x + threadIdx.x) >> 5;
    if (w >= NN) return;
    int lane = threadIdx.x & 31;
    float al = *alpha_p, bt = *beta_p, ph = *phase_p;
    float n2 = al * al + bt * bt;
    float p0 = al * al / n2, p1 = bt * bt / n2;
    float interf = 2.0f * sqrtf(p0 * p1) * cosf(ph);
    float gate = (fabsf(interf) > 0.01f) ? interf : 0.0f;
    float coll = (p0 > p1) ? 1.0f : cosf(ph);

    float4 u = *(const float4*)&d_T[(size_t)w * HD + lane * 4];
    float4 bb = *(const float4*)&bint[lane * 4];
    float4 gg = *(const float4*)&gint[lane * 4];
    float4 ee = *(const float4*)&beint[lane * 4];
    float v0 = u.x + bb.x, v1 = u.y + bb.y, v2 = u.z + bb.z, v3 = u.w + bb.w;
    float m = warp_sum(v0 + v1 + v2 + v3) * (1.0f / 128.0f);
    float q = warp_sum(v0 * v0 + v1 * v1 + v2 * v2 + v3 * v3) * (1.0f / 128.0f);
    float r = rsqrtf(q - m * m + 1e-5f);
    float hi0 = tanhf((v0 - m) * r * gg.x + ee.x);
    float hi1 = tanhf((v1 - m) * r * gg.y + ee.y);
    float hi2 = tanhf((v2 - m) * r * gg.z + ee.z);
    float hi3 = tanhf((v3 - m) * r * gg.w + ee.w);

    size_t off = (size_t)w * HD + lane * 4;
    float4 hh = *(const float4*)&d_h[off];
    float4 hf;
    hf.x = (hh.x + gate * hi0) * coll;
    hf.y = (hh.y + gate * hi1) * coll;
    hf.z = (hh.z + gate * hi2) * coll;
    hf.w = (hh.w + gate * hi3) * coll;
    *(float4*)&d_y[off] = hf;
}

// ---------------- pooling ----------------
__global__ __launch_bounds__(256) void k_pool(const int* __restrict__ batch) {
    int w = (blockIdx.x * blockDim.x + threadIdx.x) >> 5;
    if (w >= NN) return;
    int lane = threadIdx.x & 31;
    int g = clampi(batch[w], 0, NG - 1);
    float4 v = *(const float4*)&d_T[(size_t)w * HD + lane * 4];
    atomicAdd(&d_pooled[g * HD + lane * 4 + 0], v.x);
    atomicAdd(&d_pooled[g * HD + lane * 4 + 1], v.y);
    atomicAdd(&d_pooled[g * HD + lane * 4 + 2], v.z);
    atomicAdd(&d_pooled[g * HD + lane * 4 + 3], v.w);
    if (lane == 0) atomicAdd(&d_gcnt[g], 1.0f);
}

__global__ void k_finish(const float* __restrict__ bout, float* __restrict__ out) {
    int t = blockIdx.x * blockDim.x + threadIdx.x;
    if (t >= NG * HD) return;
    int c = t & 127;
    float cg = d_gcnt[t >> 7];
    out[t] = (cg > 0.0f) ? d_pooled[t] / cg + bout[c] : 0.0f;
}

// ---------------- host ----------------
extern "C" void kernel_launch(void* const* d_in, const int* in_sizes, int n_in,
                              void* d_out, int out_size) {
    const float* x     = (const float*)d_in[0];
    const int*   ei    = (const int*)d_in[1];    // int32 on device (JAX default x64 disabled)
    const int*   batch = (const int*)d_in[2];    // int32
    const float* alpha = (const float*)d_in[3];
    const float* beta  = (const float*)d_in[4];
    const float* phase = (const float*)d_in[5];
    const float* Win   = (const float*)d_in[6];
    const float* bin   = (const float*)d_in[7];
    const float* gin   = (const float*)d_in[8];
    const float* bein  = (const float*)d_in[9];
    const float* Walt  = (const float*)d_in[10];
    const float* balt  = (const float*)d_in[11];
    const float* galt  = (const float*)d_in[12];
    const float* bealt = (const float*)d_in[13];
    const float* Wself = (const float*)d_in[14];
    const float* Wmsg  = (const float*)d_in[15];
    const float* bode  = (const float*)d_in[16];
    const float* Wint  = (const float*)d_in[17];
    const float* bint  = (const float*)d_in[18];
    const float* gint  = (const float*)d_in[19];
    const float* beint = (const float*)d_in[20];
    const float* Wout  = (const float*)d_in[21];
    const float* bout  = (const float*)d_in[22];
    float* out = (float*)d_out;

    const int WB = (NN * 32 + 255) / 256;       // warp-per-node kernels: 6250 blocks
    const dim3 g2((NN + 127) / 128, 2), g1((NN + 127) / 128, 1);
    const float dt = 1.0f / (float)STEPS;

    k_zero<<<(NN + 255) / 256, 256>>>();
    k_count<<<(NE + 255) / 256, 256>>>(ei + NE);
    k_scan<<<1, 1024>>>();
    k_scatter<<<(NE + 255) / 256, 256>>>(ei, ei + NE);
    k_pack<<<64, 256>>>(Win, Walt, Wself, Wmsg, Wint, Wout);

    // head: T = x @ [W_in | W_alt]; LN+gelu+mix
    k_gemm<<<g2, 256>>>(x, 0, 1, NN, 256);
    k_head<<<WB, 256>>>(bin, gin, bein, balt, galt, bealt, alpha, beta);

    // RK4 neural ODE
    for (int s = 0; s < STEPS; s++) {
        k_gemm<<<g2, 256>>>(nullptr, 1, 2, NN, 256);
        k_spmm<<<WB, 256>>>(bode, 1.0f, 0.5f * dt, 1, 0, 0.0f);
        k_gemm<<<g2, 256>>>(nullptr, 1, 2, NN, 256);
        k_spmm<<<WB, 256>>>(bode, 2.0f, 0.5f * dt, 0, 0, 0.0f);
        k_gemm<<<g2, 256>>>(nullptr, 1, 2, NN, 256);
        k_spmm<<<WB, 256>>>(bode, 2.0f, dt, 0, 0, 0.0f);
        k_gemm<<<g2, 256>>>(nullptr, 1, 2, NN, 256);
        k_spmm<<<WB, 256>>>(bode, 1.0f, 0.0f, 0, 1, dt / 6.0f);
    }

    // tail: U = h @ (W_int_top + W_int_bot); LN+tanh+gate+collapse -> y; V = y @ W_out
    k_gemm<<<g1, 256>>>(nullptr, 2, 3, NN, 128);
    k_tail<<<WB, 256>>>(bint, gint, beint, alpha, beta, phase);
    k_gemm<<<g1, 256>>>(nullptr, 1, 4, NN, 128);

    // pooled mean per graph
    k_pool<<<WB, 256>>>(batch);
    k_finish<<<32, 256>>>(bout, out);
}

// round 14
// speedup vs baseline: 1.6705x; 1.0303x over previous
#include <cuda_runtime.h>
#include <cuda_bf16.h>
#include <math.h>

#define NN   50000
#define NE   800000
#define HD   128
#define NG   64
#define STEPS 8

// ---------------- device scratch (static globals: no allocation) ----------------
__device__ float d_h[NN * HD];
__device__ float d_y[NN * HD];
__device__ float d_kacc[NN * HD];
__device__ float d_T[NN * 256];
__device__ unsigned int d_Tb[NN * 64];   // bf16x2-packed msg half of T (cols 128..255)
// split-bf16 packed weights: layout [n][64] uint32, each uint32 = {lo16=bf16(W[2kp][n]), hi16=bf16(W[2kp+1][n])}
__device__ unsigned int d_WioH[256 * 64],  d_WioL[256 * 64];   // [W_in | W_alt]
__device__ unsigned int d_WodeH[256 * 64], d_WodeL[256 * 64];  // [W_self | W_msg]
__device__ unsigned int d_WtailH[128 * 64], d_WtailL[128 * 64]; // W_int[:128]+W_int[128:]
__device__ unsigned int d_WoutH[128 * 64], d_WoutL[128 * 64];
__device__ float d_degf[NN];
__device__ int   d_cnt[NN];
__device__ int   d_rowptr[NN + 1];
__device__ int   d_fill[NN];
__device__ int   d_col[NE];
__device__ float d_pooled[NG * HD];
__device__ float d_gcnt[NG];

// ---------------- small helpers ----------------
__device__ __forceinline__ float warp_sum(float v) {
#pragma unroll
    for (int o = 16; o > 0; o >>= 1) v += __shfl_xor_sync(0xffffffffu, v, o);
    return v;
}

__device__ __forceinline__ float gelu_tanh(float x) {
    float x3 = x * x * x;
    return 0.5f * x * (1.0f + tanhf(0.7978845608028654f * (x + 0.044715f * x3)));
}

__device__ __forceinline__ int clampi(int v, int lo, int hi) {
    return v < lo ? lo : (v > hi ? hi : v);
}

// pack two floats into bf16x2 (a -> low half / first element, b -> high half)
__device__ __forceinline__ unsigned int pack_bf2(float a, float b) {
    unsigned int r;
    asm("cvt.rn.bf16x2.f32 %0, %1, %2;" : "=r"(r) : "f"(b), "f"(a));
    return r;
}

__device__ __forceinline__ float2 unpack_bf2(unsigned int u) {
    __nv_bfloat162 h = *reinterpret_cast<__nv_bfloat162*>(&u);
    return __bfloat1622float2(h);
}

// split (a,b) into hi-pair and residual lo-pair
__device__ __forceinline__ void split2(float a, float b, unsigned int& hi, unsigned int& lo) {
    float ah = __bfloat162float(__float2bfloat16(a));
    float bh = __bfloat162float(__float2bfloat16(b));
    hi = pack_bf2(a, b);
    lo = pack_bf2(a - ah, b - bh);
}

__device__ __forceinline__ void mma16816(float c[4],
                                         unsigned int a0, unsigned int a1,
                                         unsigned int a2, unsigned int a3,
                                         unsigned int b0, unsigned int b1) {
    asm volatile(
        "mma.sync.aligned.m16n8k16.row.col.f32.bf16.bf16.f32 "
        "{%0,%1,%2,%3}, {%4,%5,%6,%7}, {%8,%9}, {%0,%1,%2,%3};"
        : "+f"(c[0]), "+f"(c[1]), "+f"(c[2]), "+f"(c[3])
        : "r"(a0), "r"(a1), "r"(a2), "r"(a3), "r"(b0), "r"(b1));
}

// ---------------- setup kernels ----------------
__global__ void k_zero() {
    int t = blockIdx.x * blockDim.x + threadIdx.x;
    if (t < NN) { d_cnt[t] = 0; d_fill[t] = 0; }
    if (t < NG * HD) d_pooled[t] = 0.0f;
    if (t < NG) d_gcnt[t] = 0.0f;
}

__global__ void k_count(const int* __restrict__ dst) {
    int e = blockIdx.x * blockDim.x + threadIdx.x;
    if (e < NE) atomicAdd(&d_cnt[clampi(dst[e], 0, NN - 1)], 1);
}

__global__ void k_scan() {
    __shared__ int sdata[1024];
    __shared__ int soff;
    int t = threadIdx.x;
    if (t == 0) soff = 0;
    __syncthreads();
    for (int base = 0; base < NN; base += 1024) {
        int i = base + t;
        int v = (i < NN) ? d_cnt[i] : 0;
        sdata[t] = v;
        __syncthreads();
#pragma unroll
        for (int off = 1; off < 1024; off <<= 1) {
            int add = (t >= off) ? sdata[t - off] : 0;
            __syncthreads();
            sdata[t] += add;
            __syncthreads();
        }
        int incl = sdata[t];
        if (i < NN) {
            d_rowptr[i] = soff + incl - v;          // exclusive prefix
            d_degf[i] = (float)(v > 0 ? v : 1);
        }
        __syncthreads();
        if (t == 0) soff += sdata[1023];
        __syncthreads();
    }
    if (t == 0) d_rowptr[NN] = soff;
}

__global__ void k_scatter(const int* __restrict__ src,
                          const int* __restrict__ dst) {
    int e = blockIdx.x * blockDim.x + threadIdx.x;
    if (e >= NE) return;
    int d = clampi(dst[e], 0, NN - 1);
    int pos = d_rowptr[d] + atomicAdd(&d_fill[d], 1);
    if (pos >= 0 && pos < NE) d_col[pos] = clampi(src[e], 0, NN - 1);
}

// pack + split weights into n-major k-pair-packed bf16 buffers
__global__ void k_pack(const float* __restrict__ Win, const float* __restrict__ Walt,
                       const float* __restrict__ Wself, const float* __restrict__ Wmsg,
                       const float* __restrict__ Wint, const float* __restrict__ Wout) {
    int t = blockIdx.x * blockDim.x + threadIdx.x;
    if (t < 256 * 64) {
        int n = t >> 6, kp = t & 63;
        int k0 = 2 * kp, k1 = 2 * kp + 1;
        float w0, w1;
        // Wio
        if (n < 128) { w0 = Win[k0 * 128 + n];  w1 = Win[k1 * 128 + n]; }
        else         { w0 = Walt[k0 * 128 + n - 128]; w1 = Walt[k1 * 128 + n - 128]; }
        split2(w0, w1, d_WioH[t], d_WioL[t]);
        // Wode
        if (n < 128) { w0 = Wself[k0 * 128 + n]; w1 = Wself[k1 * 128 + n]; }
        else         { w0 = Wmsg[k0 * 128 + n - 128]; w1 = Wmsg[k1 * 128 + n - 128]; }
        split2(w0, w1, d_WodeH[t], d_WodeL[t]);
    }
    if (t < 128 * 64) {
        int n = t >> 6, kp = t & 63;
        int k0 = 2 * kp, k1 = 2 * kp + 1;
        float w0 = Wint[k0 * 128 + n] + Wint[(k0 + 128) * 128 + n];
        float w1 = Wint[k1 * 128 + n] + Wint[(k1 + 128) * 128 + n];
        split2(w0, w1, d_WtailH[t], d_WtailL[t]);
        split2(Wout[k0 * 128 + n], Wout[k1 * 128 + n], d_WoutH[t], d_WoutL[t]);
    }
}

// ---------------- split-bf16 tensor-core GEMM: C[M,N] = A[M,128] * B[128,N] ----------------
// BM=128, BN=128, K staged in 4 chunks of 32. 256 threads = 8 warps, each 64x32 C tile.
// A fp32 -> split bf16 in smem; B preconverted. 3-term: AhBh + AhBl + AlBh, fp32 accum.
// selA: 0 = Aext, 1 = d_y, 2 = d_h.  selB: 1 = Wio, 2 = Wode, 3 = Wtail, 4 = Wout.  C = d_T.
// For selB==2 (ODE): msg half (cols>=128) stored ONLY as bf16x2 into d_Tb (fp32 store skipped).
#define SROW 20   // uint32 stride per 32-k stage row (16 pairs + 4 pad): conflict-free frags
__global__ __launch_bounds__(256) void k_gemm(const float* __restrict__ Aext,
                                              int selA, int selB, int M, int N) {
    const float* A = (selA == 0) ? Aext : ((selA == 1) ? (const float*)d_y
                                                       : (const float*)d_h);
    const unsigned int* Bh = (selB == 1) ? d_WioH
                           : (selB == 2) ? d_WodeH
                           : (selB == 3) ? d_WtailH : d_WoutH;
    const unsigned int* Bl = (selB == 1) ? d_WioL
                           : (selB == 2) ? d_WodeL
                           : (selB == 3) ? d_WtailL : d_WoutL;

    __shared__ unsigned int AsH[128 * SROW], AsL[128 * SROW];
    __shared__ unsigned int BsH[128 * SROW], BsL[128 * SROW];

    int tid = threadIdx.x;
    int wid = tid >> 5, lane = tid & 31;
    int g = lane >> 2, tg = lane & 3;
    int wm = (wid & 1) * 64;          // warp m-offset within 128
    int wn = (wid >> 1) * 32;         // warp n-offset within 128
    int m0 = blockIdx.x * 128;
    int n0 = blockIdx.y * 128;

    float c[4][4][4];
#pragma unroll
    for (int mb = 0; mb < 4; mb++)
#pragma unroll
        for (int nb = 0; nb < 4; nb++)
#pragma unroll
            for (int i = 0; i < 4; i++) c[mb][nb][i] = 0.0f;

    for (int ks = 0; ks < 4; ks++) {            // k0 = ks*32
        __syncthreads();                         // protect previous stage smem
        // stage A: 128 rows x 32 floats -> split bf16 pairs (1024 float4 loads)
#pragma unroll
        for (int i = 0; i < 4; i++) {
            int idx = tid + i * 256;             // 0..1023
            int row = idx >> 3, q = idx & 7;     // q: float4 index within 32 floats
            float4 v = make_float4(0.f, 0.f, 0.f, 0.f);
            if (m0 + row < M)
                v = *(const float4*)&A[(size_t)(m0 + row) * 128 + ks * 32 + q * 4];
            unsigned int h0, l0, h1, l1;
            split2(v.x, v.y, h0, l0);
            split2(v.z, v.w, h1, l1);
            AsH[row * SROW + q * 2]     = h0;
            AsH[row * SROW + q * 2 + 1] = h1;
            AsL[row * SROW + q * 2]     = l0;
            AsL[row * SROW + q * 2 + 1] = l1;
        }
        // stage B: 128 n-rows x 16 k-pairs = 2048 elements -> 8 iterations
#pragma unroll
        for (int i = 0; i < 8; i++) {
            int idx = tid + i * 256;             // 0..2047
            int n = idx >> 4, kp = idx & 15;     // n: 0..127
            BsH[n * SROW + kp] = Bh[(size_t)(n0 + n) * 64 + ks * 16 + kp];
            BsL[n * SROW + kp] = Bl[(size_t)(n0 + n) * 64 + ks * 16 + kp];
        }
        __syncthreads();

#pragma unroll
        for (int kc = 0; kc < 2; kc++) {         // two k16 chunks per stage
            int kb = kc * 8;                     // pair offset
            unsigned int aH[4][4], aL[4][4], bH[4][2], bL[4][2];
#pragma unroll
            for (int mb = 0; mb < 4; mb++) {
                int r0 = (wm + mb * 16 + g) * SROW + kb + tg;
                int r1 = (wm + mb * 16 + 8 + g) * SROW + kb + tg;
                aH[mb][0] = AsH[r0];     aH[mb][1] = AsH[r1];
                aH[mb][2] = AsH[r0 + 4]; aH[mb][3] = AsH[r1 + 4];
                aL[mb][0] = AsL[r0];     aL[mb][1] = AsL[r1];
                aL[mb][2] = AsL[r0 + 4]; aL[mb][3] = AsL[r1 + 4];
            }
#pragma unroll
            for (int nb = 0; nb < 4; nb++) {
                int nr = (wn + nb * 8 + g) * SROW + kb + tg;
                bH[nb][0] = BsH[nr]; bH[nb][1] = BsH[nr + 4];
                bL[nb][0] = BsL[nr]; bL[nb][1] = BsL[nr + 4];
            }
#pragma unroll
            for (int mb = 0; mb < 4; mb++)
#pragma unroll
                for (int nb = 0; nb < 4; nb++) {
                    mma16816(c[mb][nb], aH[mb][0], aH[mb][1], aH[mb][2], aH[mb][3],
                             bH[nb][0], bH[nb][1]);
                    mma16816(c[mb][nb], aH[mb][0], aH[mb][1], aH[mb][2], aH[mb][3],
                             bL[nb][0], bL[nb][1]);
                    mma16816(c[mb][nb], aL[mb][0], aL[mb][1], aL[mb][2], aL[mb][3],
                             bH[nb][0], bH[nb][1]);
                }
        }
    }

    // store C.  c[0],c[1] = cols (col, col+1) row r0; c[2],c[3] = same cols row r0+8.
    bool msg_bf16 = (selB == 2);
#pragma unroll
    for (int mb = 0; mb < 4; mb++) {
        int r0 = m0 + wm + mb * 16 + g;
        int r1 = r0 + 8;
#pragma unroll
        for (int nb = 0; nb < 4; nb++) {
            int col = n0 + wn + nb * 8 + 2 * tg;
            bool is_msg = (col >= 128);           // only possible when N==256
            if (r0 < M) {
                if (msg_bf16 && is_msg) {
                    d_Tb[(size_t)r0 * 64 + ((col - 128) >> 1)] =
                        pack_bf2(c[mb][nb][0], c[mb][nb][1]);
                } else {
                    float2 v0 = make_float2(c[mb][nb][0], c[mb][nb][1]);
                    *(float2*)&d_T[(size_t)r0 * N + col] = v0;
                }
            }
            if (r1 < M) {
                if (msg_bf16 && is_msg) {
                    d_Tb[(size_t)r1 * 64 + ((col - 128) >> 1)] =
                        pack_bf2(c[mb][nb][2], c[mb][nb][3]);
                } else {
                    float2 v1 = make_float2(c[mb][nb][2], c[mb][nb][3]);
                    *(float2*)&d_T[(size_t)r1 * N + col] = v1;
                }
            }
        }
    }
}

// ---------------- head: LN + gelu on both halves of T, mix -> h, y ----------------
__device__ __forceinline__ void ln_gelu4(float4 t, const float* __restrict__ b,
                                         const float* __restrict__ g,
                                         const float* __restrict__ be,
                                         int lane, float out[4]) {
    float4 bb = *(const float4*)&b[lane * 4];
    float4 gg = *(const float4*)&g[lane * 4];
    float4 ee = *(const float4*)&be[lane * 4];
    float v0 = t.x + bb.x, v1 = t.y + bb.y, v2 = t.z + bb.z, v3 = t.w + bb.w;
    float m = warp_sum(v0 + v1 + v2 + v3) * (1.0f / 128.0f);
    float q = warp_sum(v0 * v0 + v1 * v1 + v2 * v2 + v3 * v3) * (1.0f / 128.0f);
    float var = q - m * m;
    float r = rsqrtf(var + 1e-5f);
    out[0] = gelu_tanh((v0 - m) * r * gg.x + ee.x);
    out[1] = gelu_tanh((v1 - m) * r * gg.y + ee.y);
    out[2] = gelu_tanh((v2 - m) * r * gg.z + ee.z);
    out[3] = gelu_tanh((v3 - m) * r * gg.w + ee.w);
}

__global__ __launch_bounds__(256) void k_head(
        const float* __restrict__ bin, const float* __restrict__ gin,
        const float* __restrict__ bein,
        const float* __restrict__ balt, const float* __restrict__ galt,
        const float* __restrict__ bealt,
        const float* __restrict__ alpha_p, const float* __restrict__ beta_p) {
    int w = (blockIdx.x * blockDim.x + threadIdx.x) >> 5;
    if (w >= NN) return;
    int lane = threadIdx.x & 31;
    float al = *alpha_p, bt = *beta_p;
    float nrm = sqrtf(al * al + bt * bt);
    float s0 = fabsf(al) / nrm, s1 = fabsf(bt) / nrm;

    float4 t0 = *(const float4*)&d_T[(size_t)w * 256 + lane * 4];
    float4 t1 = *(const float4*)&d_T[(size_t)w * 256 + 128 + lane * 4];
    float g0[4], g1[4];
    ln_gelu4(t0, bin, gin, bein, lane, g0);
    ln_gelu4(t1, balt, galt, bealt, lane, g1);

    float4 hv;
    hv.x = s0 * g0[0] + s1 * g1[0];
    hv.y = s0 * g0[1] + s1 * g1[1];
    hv.z = s0 * g0[2] + s1 * g1[2];
    hv.w = s0 * g0[3] + s1 * g1[3];
    size_t off = (size_t)w * HD + lane * 4;
    *(float4*)&d_h[off] = hv;
    *(float4*)&d_y[off] = hv;
}

// ---------------- fused SpMM + tanh + RK4 bookkeeping ----------------
// One warp per node; gathers bf16x2-packed message rows (256B/row), fp32 accum.
// 4-way unrolled with independent accumulators (MLP=4).
__global__ __launch_bounds__(256) void k_spmm(const float* __restrict__ bode,
                                              float wgt, float cnext,
                                              int first, int last, float dt6) {
    int w = (blockIdx.x * blockDim.x + threadIdx.x) >> 5;
    if (w >= NN) return;
    int lane = threadIdx.x & 31;

    float4 self = *(const float4*)&d_T[(size_t)w * 256 + lane * 4];
    float4 ag0 = make_float4(0.f, 0.f, 0.f, 0.f);
    float4 ag1 = make_float4(0.f, 0.f, 0.f, 0.f);
    float4 ag2 = make_float4(0.f, 0.f, 0.f, 0.f);
    float4 ag3 = make_float4(0.f, 0.f, 0.f, 0.f);
    int beg = d_rowptr[w], end = d_rowptr[w + 1];

    int ii = beg;
    for (; ii + 4 <= end; ii += 4) {
        int s0 = __ldg(&d_col[ii]);
        int s1 = __ldg(&d_col[ii + 1]);
        int s2 = __ldg(&d_col[ii + 2]);
        int s3 = __ldg(&d_col[ii + 3]);
        uint2 u0 = *(const uint2*)&d_Tb[(size_t)s0 * 64 + lane * 2];
        uint2 u1 = *(const uint2*)&d_Tb[(size_t)s1 * 64 + lane * 2];
        uint2 u2 = *(const uint2*)&d_Tb[(size_t)s2 * 64 + lane * 2];
        uint2 u3 = *(const uint2*)&d_Tb[(size_t)s3 * 64 + lane * 2];
        float2 a, b;
        a = unpack_bf2(u0.x); b = unpack_bf2(u0.y);
        ag0.x += a.x; ag0.y += a.y; ag0.z += b.x; ag0.w += b.y;
        a = unpack_bf2(u1.x); b = unpack_bf2(u1.y);
        ag1.x += a.x; ag1.y += a.y; ag1.z += b.x; ag1.w += b.y;
        a = unpack_bf2(u2.x); b = unpack_bf2(u2.y);
        ag2.x += a.x; ag2.y += a.y; ag2.z += b.x; ag2.w += b.y;
        a = unpack_bf2(u3.x); b = unpack_bf2(u3.y);
        ag3.x += a.x; ag3.y += a.y; ag3.z += b.x; ag3.w += b.y;
    }
    for (; ii < end; ii++) {
        int s0 = __ldg(&d_col[ii]);
        uint2 u0 = *(const uint2*)&d_Tb[(size_t)s0 * 64 + lane * 2];
        float2 a = unpack_bf2(u0.x), b = unpack_bf2(u0.y);
        ag0.x += a.x; ag0.y += a.y; ag0.z += b.x; ag0.w += b.y;
    }
    float4 agg = make_float4((ag0.x + ag1.x) + (ag2.x + ag3.x),
                             (ag0.y + ag1.y) + (ag2.y + ag3.y),
                             (ag0.z + ag1.z) + (ag2.z + ag3.z),
                             (ag0.w + ag1.w) + (ag2.w + ag3.w));

    float inv = 1.0f / d_degf[w];
    float4 bb = *(const float4*)&bode[lane * 4];
    float4 kv;
    kv.x = tanhf(self.x + agg.x * inv + bb.x);
    kv.y = tanhf(self.y + agg.y * inv + bb.y);
    kv.z = tanhf(self.z + agg.z * inv + bb.z);
    kv.w = tanhf(self.w + agg.w * inv + bb.w);

    size_t off = (size_t)w * HD + lane * 4;
    float4 ka;
    if (first) {
        ka.x = wgt * kv.x; ka.y = wgt * kv.y; ka.z = wgt * kv.z; ka.w = wgt * kv.w;
    } else {
        ka = *(float4*)&d_kacc[off];
        ka.x += wgt * kv.x; ka.y += wgt * kv.y; ka.z += wgt * kv.z; ka.w += wgt * kv.w;
    }
    *(float4*)&d_kacc[off] = ka;

    float4 hh = *(const float4*)&d_h[off];
    if (last) {
        float4 hn;
        hn.x = hh.x + dt6 * ka.x; hn.y = hh.y + dt6 * ka.y;
        hn.z = hh.z + dt6 * ka.z; hn.w = hh.w + dt6 * ka.w;
        *(float4*)&d_h[off] = hn;
        *(float4*)&d_y[off] = hn;
    } else {
        float4 yn;
        yn.x = hh.x + cnext * kv.x; yn.y = hh.y + cnext * kv.y;
        yn.z = hh.z + cnext * kv.z; yn.w = hh.w + cnext * kv.w;
        *(float4*)&d_y[off] = yn;
    }
}

// ---------------- tail: LN + tanh + interference gate + collapse ----------------
__global__ __launch_bounds__(256) void k_tail(
        const float* __restrict__ bint, const float* __restrict__ gint,
        const float* __restrict__ beint,
        const float* __restrict__ alpha_p, const float* __restrict__ beta_p,
        const float* __restrict__ phase_p) {
    int w = (blockIdx.x * blockDim.x + threadIdx.x) >> 5;
    if (w >= NN) return;
    int lane = threadIdx.x & 31;
    float al = *alpha_p, bt = *beta_p, ph = *phase_p;
    float n2 = al * al + bt * bt;
    float p0 = al * al / n2, p1 = bt * bt / n2;
    float interf = 2.0f * sqrtf(p0 * p1) * cosf(ph);
    float gate = (fabsf(interf) > 0.01f) ? interf : 0.0f;
    float coll = (p0 > p1) ? 1.0f : cosf(ph);

    float4 u = *(const float4*)&d_T[(size_t)w * HD + lane * 4];
    float4 bb = *(const float4*)&bint[lane * 4];
    float4 gg = *(const float4*)&gint[lane * 4];
    float4 ee = *(const float4*)&beint[lane * 4];
    float v0 = u.x + bb.x, v1 = u.y + bb.y, v2 = u.z + bb.z, v3 = u.w + bb.w;
    float m = warp_sum(v0 + v1 + v2 + v3) * (1.0f / 128.0f);
    float q = warp_sum(v0 * v0 + v1 * v1 + v2 * v2 + v3 * v3) * (1.0f / 128.0f);
    float r = rsqrtf(q - m * m + 1e-5f);
    float hi0 = tanhf((v0 - m) * r * gg.x + ee.x);
    float hi1 = tanhf((v1 - m) * r * gg.y + ee.y);
    float hi2 = tanhf((v2 - m) * r * gg.z + ee.z);
    float hi3 = tanhf((v3 - m) * r * gg.w + ee.w);

    size_t off = (size_t)w * HD + lane * 4;
    float4 hh = *(const float4*)&d_h[off];
    float4 hf;
    hf.x = (hh.x + gate * hi0) * coll;
    hf.y = (hh.y + gate * hi1) * coll;
    hf.z = (hh.z + gate * hi2) * coll;
    hf.w = (hh.w + gate * hi3) * coll;
    *(float4*)&d_y[off] = hf;
}

// ---------------- pooling ----------------
__global__ __launch_bounds__(256) void k_pool(const int* __restrict__ batch) {
    int w = (blockIdx.x * blockDim.x + threadIdx.x) >> 5;
    if (w >= NN) return;
    int lane = threadIdx.x & 31;
    int g = clampi(batch[w], 0, NG - 1);
    float4 v = *(const float4*)&d_T[(size_t)w * HD + lane * 4];
    atomicAdd(&d_pooled[g * HD + lane * 4 + 0], v.x);
    atomicAdd(&d_pooled[g * HD + lane * 4 + 1], v.y);
    atomicAdd(&d_pooled[g * HD + lane * 4 + 2], v.z);
    atomicAdd(&d_pooled[g * HD + lane * 4 + 3], v.w);
    if (lane == 0) atomicAdd(&d_gcnt[g], 1.0f);
}

__global__ void k_finish(const float* __restrict__ bout, float* __restrict__ out) {
    int t = blockIdx.x * blockDim.x + threadIdx.x;
    if (t >= NG * HD) return;
    int c = t & 127;
    float cg = d_gcnt[t >> 7];
    out[t] = (cg > 0.0f) ? d_pooled[t] / cg + bout[c] : 0.0f;
}

// ---------------- host ----------------
extern "C" void kernel_launch(void* const* d_in, const int* in_sizes, int n_in,
                              void* d_out, int out_size) {
    const float* x     = (const float*)d_in[0];
    const int*   ei    = (const int*)d_in[1];    // int32 on device (JAX default x64 disabled)
    const int*   batch = (const int*)d_in[2];    // int32
    const float* alpha = (const float*)d_in[3];
    const float* beta  = (const float*)d_in[4];
    const float* phase = (const float*)d_in[5];
    const float* Win   = (const float*)d_in[6];
    const float* bin   = (const float*)d_in[7];
    const float* gin   = (const float*)d_in[8];
    const float* bein  = (const float*)d_in[9];
    const float* Walt  = (const float*)d_in[10];
    const float* balt  = (const float*)d_in[11];
    const float* galt  = (const float*)d_in[12];
    const float* bealt = (const float*)d_in[13];
    const float* Wself = (const float*)d_in[14];
    const float* Wmsg  = (const float*)d_in[15];
    const float* bode  = (const float*)d_in[16];
    const float* Wint  = (const float*)d_in[17];
    const float* bint  = (const float*)d_in[18];
    const float* gint  = (const float*)d_in[19];
    const float* beint = (const float*)d_in[20];
    const float* Wout  = (const float*)d_in[21];
    const float* bout  = (const float*)d_in[22];
    float* out = (float*)d_out;

    const int WB = (NN * 32 + 255) / 256;       // warp-per-node kernels: 6250 blocks
    const dim3 g2((NN + 127) / 128, 2), g1((NN + 127) / 128, 1);
    const float dt = 1.0f / (float)STEPS;

    k_zero<<<(NN + 255) / 256, 256>>>();
    k_count<<<(NE + 255) / 256, 256>>>(ei + NE);
    k_scan<<<1, 1024>>>();
    k_scatter<<<(NE + 255) / 256, 256>>>(ei, ei + NE);
    k_pack<<<64, 256>>>(Win, Walt, Wself, Wmsg, Wint, Wout);

    // head: T = x @ [W_in | W_alt]; LN+gelu+mix
    k_gemm<<<g2, 256>>>(x, 0, 1, NN, 256);
    k_head<<<WB, 256>>>(bin, gin, bein, balt, galt, bealt, alpha, beta);

    // RK4 neural ODE
    for (int s = 0; s < STEPS; s++) {
        k_gemm<<<g2, 256>>>(nullptr, 1, 2, NN, 256);
        k_spmm<<<WB, 256>>>(bode, 1.0f, 0.5f * dt, 1, 0, 0.0f);
        k_gemm<<<g2, 256>>>(nullptr, 1, 2, NN, 256);
        k_spmm<<<WB, 256>>>(bode, 2.0f, 0.5f * dt, 0, 0, 0.0f);
        k_gemm<<<g2, 256>>>(nullptr, 1, 2, NN, 256);
        k_spmm<<<WB, 256>>>(bode, 2.0f, dt, 0, 0, 0.0f);
        k_gemm<<<g2, 256>>>(nullptr, 1, 2, NN, 256);
        k_spmm<<<WB, 256>>>(bode, 1.0f, 0.0f, 0, 1, dt / 6.0f);
    }

    // tail: U = h @ (W_int_top + W_int_bot); LN+tanh+gate+collapse -> y; V = y @ W_out
    k_gemm<<<g1, 256>>>(nullptr, 2, 3, NN, 128);
    k_tail<<<WB, 256>>>(bint, gint, beint, alpha, beta, phase);
    k_gemm<<<g1, 256>>>(nullptr, 1, 4, NN, 128);

    // pooled mean per graph
    k_pool<<<WB, 256>>>(batch);
    k_finish<<<32, 256>>>(bout, out);
}